// round 3
// baseline (speedup 1.0000x reference)
#include <cuda_runtime.h>

#define G_NUM   1000
#define NPG     200
#define NPAD    208     // padded rows (16 warps * 13 j-steps)
#define KNN     5
#define MD      128
#define THREADS 512

typedef unsigned long long ull;

__device__ __forceinline__ ull pack2(float lo, float hi) {
    ull r; asm("mov.b64 %0, {%1, %2};" : "=l"(r) : "f"(lo), "f"(hi)); return r;
}
__device__ __forceinline__ ull dup2(float v) { return pack2(v, v); }
__device__ __forceinline__ ull fma2(ull a, ull b, ull c) {
    ull d; asm("fma.rn.f32x2 %0, %1, %2, %3;" : "=l"(d) : "l"(a), "l"(b), "l"(c)); return d;
}
__device__ __forceinline__ void unpack2(ull v, float& lo, float& hi) {
    asm("mov.b64 {%0, %1}, %2;" : "=f"(lo), "=f"(hi) : "l"(v));
}

// dynamic smem layout (float offsets)
#define XS_OFF   0                      // 208*128 = 26624 floats (x/h buffer, pad rows zero)
#define W_OFF    26624                  // 128*128 = 16384 floats
#define POS_OFF  43008                  // 200*3   = 600 floats
#define NBR_OFF  43608                  // 200*5   = 1000 ints
#define SM_OFF   44608                  // 736 floats: partial[4][128] + pooled[128] + h1[64] + h2[32]
#define SMEM_FLOATS 45344               // 181376 bytes

extern "C" __global__ void __launch_bounds__(THREADS, 1)
egnn_fused_kernel(const int* __restrict__ z, const float* __restrict__ pos,
                  const float* __restrict__ emb, const float* __restrict__ convW,
                  const float* __restrict__ convb, const float* __restrict__ rW1,
                  const float* __restrict__ rb1, const float* __restrict__ rW2,
                  const float* __restrict__ rb2, const float* __restrict__ rW3,
                  const float* __restrict__ rb3, float* __restrict__ out)
{
    extern __shared__ float smem[];
    float* xs   = smem + XS_OFF;
    float* Wsm  = smem + W_OFF;
    float* poss = smem + POS_OFF;
    int*   nbr  = (int*)(smem + NBR_OFF);
    float* sm   = smem + SM_OFF;

    const int g    = blockIdx.x;
    const int tid  = threadIdx.x;
    const int warp = tid >> 5;
    const int lane = tid & 31;
    const int c0   = lane * 4;

    // ---- phase 1: everyone loads pos (600 floats) ----
    for (int i = tid; i < NPG * 3; i += THREADS)
        poss[i] = pos[g * NPG * 3 + i];
    __syncthreads();

    // ---- phase 2 (warp-specialized): warps 0-6 kNN | warps 7-15 embedding gather ----
    if (warp < 7) {
        // kNN: top-5 nearest (stable tie-break == jax.lax.top_k: lower index wins)
        if (tid < NPG) {
            const int i = tid;
            float xi = poss[i*3+0], yi = poss[i*3+1], zi = poss[i*3+2];
            float bd0=1e30f,bd1=1e30f,bd2=1e30f,bd3=1e30f,bd4=1e30f;
            int   bi0=0,   bi1=0,   bi2=0,   bi3=0,   bi4=0;
            for (int j = 0; j < NPG; j++) {
                if (j == i) continue;
                float dx = xi - poss[j*3+0];
                float dy = yi - poss[j*3+1];
                float dz = zi - poss[j*3+2];
                float d2 = dx*dx + dy*dy + dz*dz;
                if (d2 < bd4) {
                    if (d2 < bd0)      { bd4=bd3;bi4=bi3; bd3=bd2;bi3=bi2; bd2=bd1;bi2=bi1; bd1=bd0;bi1=bi0; bd0=d2;bi0=j; }
                    else if (d2 < bd1) { bd4=bd3;bi4=bi3; bd3=bd2;bi3=bi2; bd2=bd1;bi2=bi1; bd1=d2;bi1=j; }
                    else if (d2 < bd2) { bd4=bd3;bi4=bi3; bd3=bd2;bi3=bi2; bd2=d2;bi2=j; }
                    else if (d2 < bd3) { bd4=bd3;bi4=bi3; bd3=d2;bi3=j; }
                    else               { bd4=d2;bi4=j; }
                }
            }
            nbr[i*KNN+0]=bi0; nbr[i*KNN+1]=bi1; nbr[i*KNN+2]=bi2;
            nbr[i*KNN+3]=bi3; nbr[i*KNN+4]=bi4;
        }
    } else {
        // embedding gather: lane owns one float4 of the row; pad rows zeroed
        for (int r = warp - 7; r < NPAD; r += 9) {
            float4 v;
            if (r < NPG) {
                int zr = z[g * NPG + r];
                v = *reinterpret_cast<const float4*>(&emb[zr * MD + c0]);
            } else {
                v = make_float4(0.f, 0.f, 0.f, 0.f);
            }
            *reinterpret_cast<float4*>(&xs[r * MD + c0]) = v;
        }
    }
    __syncthreads();

    // deg == K+1 == 6 for every node (knn gives exactly K in-edges) -> constant norm
    const float dis  = rsqrtf(6.0f);
    const float inv6 = dis * dis;

    // ---- 3 GCN layers, fully in SMEM/registers ----
    for (int l = 0; l < 3; l++) {
        // vectorized W load: 16384 floats = 4096 float4 / 512 threads = 8 iters
        {
            const float4* Wg = reinterpret_cast<const float4*>(convW + l * MD * MD);
            float4*       Ws = reinterpret_cast<float4*>(Wsm);
            #pragma unroll
            for (int it = 0; it < 8; it++)
                Ws[tid + it * THREADS] = Wg[tid + it * THREADS];
        }
        __syncthreads();

        // GEMM h = x @ W over 208 padded rows. Warp w owns rows r = w + 16*j,
        // j = 0..12 (uniform, no guards). Lane owns cols [c0, c0+4) as 2 packed f32x2.
        ull acc[13][2];
        #pragma unroll
        for (int j = 0; j < 13; j++) { acc[j][0] = 0ull; acc[j][1] = 0ull; }

        #pragma unroll 2
        for (int k4 = 0; k4 < 32; k4++) {
            ull w2[4][2];
            #pragma unroll
            for (int kk = 0; kk < 4; kk++) {
                float4 wv = *reinterpret_cast<const float4*>(&Wsm[(k4*4+kk)*MD + c0]);
                w2[kk][0] = pack2(wv.x, wv.y);
                w2[kk][1] = pack2(wv.z, wv.w);
            }
            #pragma unroll
            for (int j = 0; j < 13; j++) {
                const int r = warp + 16 * j;
                float4 xv = *reinterpret_cast<const float4*>(&xs[r*MD + k4*4]);
                ull x0 = dup2(xv.x), x1 = dup2(xv.y), x2 = dup2(xv.z), x3 = dup2(xv.w);
                acc[j][0] = fma2(x0, w2[0][0], acc[j][0]);
                acc[j][1] = fma2(x0, w2[0][1], acc[j][1]);
                acc[j][0] = fma2(x1, w2[1][0], acc[j][0]);
                acc[j][1] = fma2(x1, w2[1][1], acc[j][1]);
                acc[j][0] = fma2(x2, w2[2][0], acc[j][0]);
                acc[j][1] = fma2(x2, w2[2][1], acc[j][1]);
                acc[j][0] = fma2(x3, w2[3][0], acc[j][0]);
                acc[j][1] = fma2(x3, w2[3][1], acc[j][1]);
            }
        }
        __syncthreads();   // all x reads complete -> safe to overwrite xs with h

        #pragma unroll
        for (int j = 0; j < 13; j++) {
            const int r = warp + 16 * j;      // pad rows get h=0 (zero inputs)
            float4 h4;
            unpack2(acc[j][0], h4.x, h4.y);
            unpack2(acc[j][1], h4.z, h4.w);
            *reinterpret_cast<float4*>(&xs[r*MD + c0]) = h4;
        }
        __syncthreads();

        // aggregate: x'[r] = relu((h[r] + sum_{5 nbrs} h[nbr]) / 6 + b), r < 200 only
        float4 bias4 = *reinterpret_cast<const float4*>(&convb[l*MD + c0]);
        float racc[13][4];
        #pragma unroll
        for (int j = 0; j < 13; j++) {
            const int r = warp + 16 * j;
            if (r < NPG) {
                float4 a = *reinterpret_cast<const float4*>(&xs[r*MD + c0]);
                float sx = a.x, sy = a.y, sz = a.z, sw = a.w;
                #pragma unroll
                for (int e = 0; e < KNN; e++) {
                    int nb = nbr[r*KNN + e];
                    float4 hn = *reinterpret_cast<const float4*>(&xs[nb*MD + c0]);
                    sx += hn.x; sy += hn.y; sz += hn.z; sw += hn.w;
                }
                racc[j][0] = fmaxf(sx * inv6 + bias4.x, 0.0f);
                racc[j][1] = fmaxf(sy * inv6 + bias4.y, 0.0f);
                racc[j][2] = fmaxf(sz * inv6 + bias4.z, 0.0f);
                racc[j][3] = fmaxf(sw * inv6 + bias4.w, 0.0f);
            }
        }
        __syncthreads();   // all h reads complete -> safe to overwrite with x'
        #pragma unroll
        for (int j = 0; j < 13; j++) {
            const int r = warp + 16 * j;
            if (r < NPG) {
                float4 o;
                o.x = racc[j][0]; o.y = racc[j][1]; o.z = racc[j][2]; o.w = racc[j][3];
                *reinterpret_cast<float4*>(&xs[r*MD + c0]) = o;
            }
            // pad rows keep h=0 -> still zero for the next layer's GEMM
        }
        __syncthreads();
    }

    // ---- mean pool over 200 nodes (all 512 threads: 4 partials per column) ----
    {
        const int col = tid & 127;
        const int q   = tid >> 7;          // 0..3, rows [q*50, q*50+50)
        float s = 0.0f;
        for (int r = q * 50; r < q * 50 + 50; r++) s += xs[r*MD + col];
        sm[q * MD + col] = s;
    }
    __syncthreads();
    if (tid < MD) {
        float s = sm[tid] + sm[MD + tid] + sm[2*MD + tid] + sm[3*MD + tid];
        sm[4*MD + tid] = s * (1.0f / 200.0f);
    }
    __syncthreads();

    // ---- regressor MLP 128 -> 64 -> 32 -> 1 ----
    const float* pooled = sm + 4*MD;
    if (tid < 64) {
        float s = rb1[tid];
        for (int c = 0; c < MD; c++) s += pooled[c] * rW1[c*64 + tid];
        sm[5*MD + tid] = fmaxf(s, 0.0f);
    }
    __syncthreads();
    if (tid < 32) {
        float s = rb2[tid];
        for (int c = 0; c < 64; c++) s += sm[5*MD + c] * rW2[c*32 + tid];
        sm[5*MD + 64 + tid] = fmaxf(s, 0.0f);
    }
    __syncthreads();
    if (tid == 0) {
        float s = rb3[0];
        for (int c = 0; c < 32; c++) s += sm[5*MD + 64 + c] * rW3[c];
        out[g] = s;
    }
}

extern "C" void kernel_launch(void* const* d_in, const int* in_sizes, int n_in,
                              void* d_out, int out_size) {
    const int*   z     = (const int*)  d_in[0];
    const float* pos   = (const float*)d_in[1];
    // d_in[2] = batch (implicit arange(N)//NPG) -- unused
    const float* emb   = (const float*)d_in[3];
    const float* convW = (const float*)d_in[4];
    const float* convb = (const float*)d_in[5];
    const float* rW1   = (const float*)d_in[6];
    const float* rb1   = (const float*)d_in[7];
    const float* rW2   = (const float*)d_in[8];
    const float* rb2   = (const float*)d_in[9];
    const float* rW3   = (const float*)d_in[10];
    const float* rb3   = (const float*)d_in[11];

    size_t smem_bytes = SMEM_FLOATS * sizeof(float);
    cudaFuncSetAttribute(egnn_fused_kernel,
                         cudaFuncAttributeMaxDynamicSharedMemorySize, (int)smem_bytes);
    egnn_fused_kernel<<<G_NUM, THREADS, smem_bytes>>>(
        z, pos, emb, convW, convb, rW1, rb1, rW2, rb2, rW3, rb3, (float*)d_out);
}

// round 17
// speedup vs baseline: 1.4531x; 1.4531x over previous
#include <cuda_runtime.h>
#include <cuda_bf16.h>
#include <cstdint>

#define G_NUM   1000
#define NPG     200
#define KNN     5
#define MD      128
#define THREADS 512
#define RSTRIDE 272          // bytes per bf16 plane row (136 bf16; 272=16*17 -> LDSM conflict-free)

// ---- dynamic smem byte offsets ----
#define XH_B   0             // x/A hi plane [208][136] bf16 = 56576 B
#define XL_B   56576         // x/A lo plane
#define WH_B   113152        // W^T hi plane [128][136] bf16 = 34816 B
#define WL_B   147968        // W^T lo plane
#define POS_B  182784        // 600 f32
#define NBR_B  185184        // 1000 i32
#define BIAS_B 189184        // 128 f32
#define SM_B   189696        // 736 f32: partial 4*128, pooled 128, h1 64, h2 32
#define SMEM_BYTES 192640

// ---------------- helpers ----------------
__device__ __forceinline__ uint32_t smem_u32(const void* p) {
    uint32_t a;
    asm("{ .reg .u64 t; cvta.to.shared.u64 t, %1; cvt.u32.u64 %0, t; }" : "=r"(a) : "l"(p));
    return a;
}
// pack two floats -> bf16x2, first arg in LOW half (even col), second in HIGH (odd col)
__device__ __forceinline__ uint32_t bfpack(float lo, float hi) {
    uint32_t r; asm("cvt.rn.bf16x2.f32 %0, %1, %2;" : "=r"(r) : "f"(hi), "f"(lo)); return r;
}
// exact bf16->f32 of low / high half of a packed b32
__device__ __forceinline__ float bflo(uint32_t v) { return __uint_as_float(v << 16); }
__device__ __forceinline__ float bfhi(uint32_t v) { return __uint_as_float(v & 0xFFFF0000u); }

#define LDSM_X4(r, addr) \
    asm volatile("ldmatrix.sync.aligned.m8n8.x4.shared.b16 {%0,%1,%2,%3}, [%4];" \
        : "=r"((r)[0]), "=r"((r)[1]), "=r"((r)[2]), "=r"((r)[3]) : "r"(addr))

#define MMA16816(d, a, b0, b1) \
    asm volatile("mma.sync.aligned.m16n8k16.row.col.f32.bf16.bf16.f32 " \
        "{%0,%1,%2,%3}, {%4,%5,%6,%7}, {%8,%9}, {%0,%1,%2,%3};" \
        : "+f"((d)[0]), "+f"((d)[1]), "+f"((d)[2]), "+f"((d)[3]) \
        : "r"((a)[0]), "r"((a)[1]), "r"((a)[2]), "r"((a)[3]), "r"(b0), "r"(b1))

extern "C" __global__ void __launch_bounds__(THREADS, 1)
egnn_hmma_kernel(const int* __restrict__ z, const float* __restrict__ pos,
                 const float* __restrict__ emb, const float* __restrict__ convW,
                 const float* __restrict__ convb, const float* __restrict__ rW1,
                 const float* __restrict__ rb1, const float* __restrict__ rW2,
                 const float* __restrict__ rb2, const float* __restrict__ rW3,
                 const float* __restrict__ rb3, float* __restrict__ out)
{
    extern __shared__ char smemc[];
    float* poss = (float*)(smemc + POS_B);
    int*   nbr  = (int*)  (smemc + NBR_B);
    float* bias = (float*)(smemc + BIAS_B);
    float* sm   = (float*)(smemc + SM_B);

    const int g    = blockIdx.x;
    const int tid  = threadIdx.x;
    const int warp = tid >> 5;
    const int lane = tid & 31;
    const uint32_t sb = smem_u32(smemc);

    // ---- pos load ----
    for (int i = tid; i < NPG * 3; i += THREADS)
        poss[i] = pos[g * NPG * 3 + i];
    __syncthreads();

    // ---- warp-specialized prologue: warps 0-6 kNN | warps 7-15 embedding -> hi/lo planes ----
    if (warp < 7) {
        if (tid < NPG) {
            const int i = tid;
            float xi = poss[i*3+0], yi = poss[i*3+1], zi = poss[i*3+2];
            float bd0=1e30f,bd1=1e30f,bd2=1e30f,bd3=1e30f,bd4=1e30f;
            int   bi0=0,   bi1=0,   bi2=0,   bi3=0,   bi4=0;
            for (int j = 0; j < NPG; j++) {
                if (j == i) continue;
                float dx = xi - poss[j*3+0];
                float dy = yi - poss[j*3+1];
                float dz = zi - poss[j*3+2];
                float d2 = dx*dx + dy*dy + dz*dz;
                if (d2 < bd4) {
                    if (d2 < bd0)      { bd4=bd3;bi4=bi3; bd3=bd2;bi3=bi2; bd2=bd1;bi2=bi1; bd1=bd0;bi1=bi0; bd0=d2;bi0=j; }
                    else if (d2 < bd1) { bd4=bd3;bi4=bi3; bd3=bd2;bi3=bi2; bd2=bd1;bi2=bi1; bd1=d2;bi1=j; }
                    else if (d2 < bd2) { bd4=bd3;bi4=bi3; bd3=bd2;bi3=bi2; bd2=d2;bi2=j; }
                    else if (d2 < bd3) { bd4=bd3;bi4=bi3; bd3=d2;bi3=j; }
                    else               { bd4=d2;bi4=j; }
                }
            }
            nbr[i*KNN+0]=bi0; nbr[i*KNN+1]=bi1; nbr[i*KNN+2]=bi2;
            nbr[i*KNN+3]=bi3; nbr[i*KNN+4]=bi4;
        }
    } else {
        // embedding rows 0..199 as hi/lo; pad rows 200..207 zeroed (LDSM-read, never output)
        for (int r = warp - 7; r < 208; r += 9) {
            uint2 hv = make_uint2(0u, 0u), lv = make_uint2(0u, 0u);
            if (r < NPG) {
                int zr = z[g * NPG + r];
                float4 v = *reinterpret_cast<const float4*>(&emb[zr * MD + lane * 4]);
                hv.x = bfpack(v.x, v.y); hv.y = bfpack(v.z, v.w);
                lv.x = bfpack(v.x - bflo(hv.x), v.y - bfhi(hv.x));
                lv.y = bfpack(v.z - bflo(hv.y), v.w - bfhi(hv.y));
            }
            *reinterpret_cast<uint2*>(smemc + XH_B + r * RSTRIDE + lane * 8) = hv;
            *reinterpret_cast<uint2*>(smemc + XL_B + r * RSTRIDE + lane * 8) = lv;
        }
    }
    __syncthreads();

    const float inv6 = 1.0f / 6.0f;    // knn => deg == 6 uniformly

    // ---- 3 GCN layers ----
    for (int l = 0; l < 3; l++) {
        // (a) W^T hi/lo split into planes + bias
        {
            const float* Wg = convW + l * MD * MD;
            const int n  = tid >> 2;       // 0..127 output col
            const int kc = tid & 3;        // k chunk of 32
            #pragma unroll
            for (int i = 0; i < 8; i++) {
                int k0 = kc * 32 + i * 4;
                float w0 = Wg[(k0+0)*MD + n], w1 = Wg[(k0+1)*MD + n];
                float w2 = Wg[(k0+2)*MD + n], w3 = Wg[(k0+3)*MD + n];
                uint2 hv, lv;
                hv.x = bfpack(w0, w1); hv.y = bfpack(w2, w3);
                lv.x = bfpack(w0 - bflo(hv.x), w1 - bfhi(hv.x));
                lv.y = bfpack(w2 - bflo(hv.y), w3 - bfhi(hv.y));
                *reinterpret_cast<uint2*>(smemc + WH_B + n * RSTRIDE + k0 * 2) = hv;
                *reinterpret_cast<uint2*>(smemc + WL_B + n * RSTRIDE + k0 * 2) = lv;
            }
            if (tid < MD) bias[tid] = convb[l * MD + tid];
        }

        // (b) aggregate a = x + sum_nbr x into fp32 regs (read all, then write in place)
        float av[13][4];
        #pragma unroll
        for (int j = 0; j < 13; j++) {
            const int r = warp + 16 * j;
            if (r < NPG) {
                const uint32_t off = (uint32_t)r * RSTRIDE + lane * 8;
                uint2 hv = *reinterpret_cast<uint2*>(smemc + XH_B + off);
                uint2 lv = *reinterpret_cast<uint2*>(smemc + XL_B + off);
                float s0 = bflo(hv.x) + bflo(lv.x), s1 = bfhi(hv.x) + bfhi(lv.x);
                float s2 = bflo(hv.y) + bflo(lv.y), s3 = bfhi(hv.y) + bfhi(lv.y);
                #pragma unroll
                for (int e = 0; e < KNN; e++) {
                    const uint32_t no = (uint32_t)nbr[r * KNN + e] * RSTRIDE + lane * 8;
                    uint2 nh = *reinterpret_cast<uint2*>(smemc + XH_B + no);
                    uint2 nl = *reinterpret_cast<uint2*>(smemc + XL_B + no);
                    s0 += bflo(nh.x) + bflo(nl.x); s1 += bfhi(nh.x) + bfhi(nl.x);
                    s2 += bflo(nh.y) + bflo(nl.y); s3 += bfhi(nh.y) + bfhi(nl.y);
                }
                av[j][0] = s0; av[j][1] = s1; av[j][2] = s2; av[j][3] = s3;
            }
        }
        __syncthreads();   // all reads of x done -> safe to overwrite planes with A
        #pragma unroll
        for (int j = 0; j < 13; j++) {
            const int r = warp + 16 * j;
            if (r < NPG) {
                uint2 hv, lv;
                hv.x = bfpack(av[j][0], av[j][1]); hv.y = bfpack(av[j][2], av[j][3]);
                lv.x = bfpack(av[j][0] - bflo(hv.x), av[j][1] - bfhi(hv.x));
                lv.y = bfpack(av[j][2] - bflo(hv.y), av[j][3] - bfhi(hv.y));
                const uint32_t off = (uint32_t)r * RSTRIDE + lane * 8;
                *reinterpret_cast<uint2*>(smemc + XH_B + off) = hv;
                *reinterpret_cast<uint2*>(smemc + XL_B + off) = lv;
            }
        }
        __syncthreads();

        // (c) GEMM via mma.sync: tasks (m-tile, n-half); warp w -> tasks w, w+16
        float acc[2][8][4];
        #pragma unroll
        for (int tt = 0; tt < 2; tt++)
            #pragma unroll
            for (int j = 0; j < 8; j++)
                #pragma unroll
                for (int q = 0; q < 4; q++) acc[tt][j][q] = 0.0f;

        const int grp = lane >> 3;
        #pragma unroll
        for (int tt = 0; tt < 2; tt++) {
            const int t = warp + 16 * tt;
            if (t < 26) {
                const int mt = t % 13, nh = t / 13;
                const uint32_t arow  = (uint32_t)(mt * 16 + ((grp & 1) * 8) + (lane & 7));
                const uint32_t abase = sb + XH_B + arow * RSTRIDE + (uint32_t)(lane >> 4) * 16;
                uint32_t bb[4];
                #pragma unroll
                for (int p = 0; p < 4; p++) {
                    const int n8 = nh * 8 + 2 * p + (grp >> 1);
                    bb[p] = sb + WH_B + (uint32_t)(n8 * 8 + (lane & 7)) * RSTRIDE + (grp & 1) * 16;
                }
                #pragma unroll
                for (int kk = 0; kk < 8; kk++) {
                    uint32_t ah[4], al[4];
                    LDSM_X4(ah, abase + kk * 32);
                    LDSM_X4(al, abase + (XL_B - XH_B) + kk * 32);
                    #pragma unroll
                    for (int p = 0; p < 4; p++) {
                        uint32_t bh[4], bl[4];
                        LDSM_X4(bh, bb[p] + kk * 32);
                        LDSM_X4(bl, bb[p] + (WL_B - WH_B) + kk * 32);
                        MMA16816(acc[tt][2*p],   ah, bh[0], bh[1]);
                        MMA16816(acc[tt][2*p+1], ah, bh[2], bh[3]);
                        MMA16816(acc[tt][2*p],   ah, bl[0], bl[1]);
                        MMA16816(acc[tt][2*p+1], ah, bl[2], bl[3]);
                        MMA16816(acc[tt][2*p],   al, bh[0], bh[1]);
                        MMA16816(acc[tt][2*p+1], al, bh[2], bh[3]);
                    }
                }
            }
        }
        __syncthreads();   // all A/W reads done -> safe to overwrite planes with x'

        // (d) epilogue: x' = relu(D/6 + b) -> hi/lo planes
        #pragma unroll
        for (int tt = 0; tt < 2; tt++) {
            const int t = warp + 16 * tt;
            if (t < 26) {
                const int mt = t % 13, nh = t / 13;
                const uint32_t rA = (uint32_t)(mt * 16 + (lane >> 2));
                const uint32_t rB = rA + 8;
                #pragma unroll
                for (int j = 0; j < 8; j++) {
                    const int n0 = nh * 64 + j * 8 + (lane & 3) * 2;
                    float2 bv = *reinterpret_cast<float2*>(smemc + BIAS_B + n0 * 4);
                    float vA0 = fmaxf(acc[tt][j][0] * inv6 + bv.x, 0.0f);
                    float vA1 = fmaxf(acc[tt][j][1] * inv6 + bv.y, 0.0f);
                    float vB0 = fmaxf(acc[tt][j][2] * inv6 + bv.x, 0.0f);
                    float vB1 = fmaxf(acc[tt][j][3] * inv6 + bv.y, 0.0f);
                    uint32_t hA = bfpack(vA0, vA1);
                    uint32_t lA = bfpack(vA0 - bflo(hA), vA1 - bfhi(hA));
                    uint32_t hB = bfpack(vB0, vB1);
                    uint32_t lB = bfpack(vB0 - bflo(hB), vB1 - bfhi(hB));
                    *reinterpret_cast<uint32_t*>(smemc + XH_B + rA * RSTRIDE + n0 * 2) = hA;
                    *reinterpret_cast<uint32_t*>(smemc + XL_B + rA * RSTRIDE + n0 * 2) = lA;
                    *reinterpret_cast<uint32_t*>(smemc + XH_B + rB * RSTRIDE + n0 * 2) = hB;
                    *reinterpret_cast<uint32_t*>(smemc + XL_B + rB * RSTRIDE + n0 * 2) = lB;
                }
            }
        }
        __syncthreads();
    }

    // ---- mean pool over 200 nodes (4 partials per column) ----
    {
        const int col = tid & 127;
        const int q   = tid >> 7;
        float s = 0.0f;
        for (int r = q * 50; r < q * 50 + 50; r++) {
            uint32_t vh = *reinterpret_cast<uint32_t*>(smemc + XH_B + r * RSTRIDE + (col >> 1) * 4);
            uint32_t vl = *reinterpret_cast<uint32_t*>(smemc + XL_B + r * RSTRIDE + (col >> 1) * 4);
            s += (col & 1) ? (bfhi(vh) + bfhi(vl)) : (bflo(vh) + bflo(vl));
        }
        sm[q * MD + col] = s;
    }
    __syncthreads();
    if (tid < MD) {
        float s = sm[tid] + sm[MD + tid] + sm[2*MD + tid] + sm[3*MD + tid];
        sm[4*MD + tid] = s * (1.0f / 200.0f);
    }
    __syncthreads();

    // ---- regressor MLP 128 -> 64 -> 32 -> 1 ----
    const float* pooled = sm + 4 * MD;
    if (tid < 64) {
        float s = rb1[tid];
        for (int c = 0; c < MD; c++) s += pooled[c] * rW1[c*64 + tid];
        sm[5*MD + tid] = fmaxf(s, 0.0f);
    }
    __syncthreads();
    if (tid < 32) {
        float s = rb2[tid];
        for (int c = 0; c < 64; c++) s += sm[5*MD + c] * rW2[c*32 + tid];
        sm[5*MD + 64 + tid] = fmaxf(s, 0.0f);
    }
    __syncthreads();
    if (tid == 0) {
        float s = rb3[0];
        for (int c = 0; c < 32; c++) s += sm[5*MD + 64 + c] * rW3[c];
        out[g] = s;
    }
}

extern "C" void kernel_launch(void* const* d_in, const int* in_sizes, int n_in,
                              void* d_out, int out_size) {
    const int*   z     = (const int*)  d_in[0];
    const float* pos   = (const float*)d_in[1];
    // d_in[2] = batch (implicit arange(N)//NPG) -- unused
    const float* emb   = (const float*)d_in[3];
    const float* convW = (const float*)d_in[4];
    const float* convb = (const float*)d_in[5];
    const float* rW1   = (const float*)d_in[6];
    const float* rb1   = (const float*)d_in[7];
    const float* rW2   = (const float*)d_in[8];
    const float* rb2   = (const float*)d_in[9];
    const float* rW3   = (const float*)d_in[10];
    const float* rb3   = (const float*)d_in[11];

    cudaFuncSetAttribute(egnn_hmma_kernel,
                         cudaFuncAttributeMaxDynamicSharedMemorySize, SMEM_BYTES);
    egnn_hmma_kernel<<<G_NUM, THREADS, SMEM_BYTES>>>(
        z, pos, emb, convW, convb, rW1, rb1, rW2, rb2, rW3, rb3, (float*)d_out);
}